// round 2
// baseline (speedup 1.0000x reference)
#include <cuda_runtime.h>
#include <cstdint>

#define N_NODES 50000
#define N_EDGES 800000
#define E_TOT   (N_EDGES + N_NODES)
#define IN_DIM  256
#define OUT_DIM 256   // N_HEADS * HEAD_DIM
#define NEG_SLOPE 0.2f

// ---------------- scratch (static device globals; no runtime allocation) ---
__device__ __align__(16) float g_xp[(size_t)N_NODES * OUT_DIM];   // projected features [N,256]
__device__ __align__(16) float g_asrc[N_NODES * 4];               // per-node src logits [N,4]
__device__ __align__(16) float g_adst[N_NODES * 4];               // per-node dst logits [N,4]
__device__ __align__(16) float g_denom[N_NODES * 4];              // softmax denominators [N,4]
__device__ __align__(16) float g_ee[(size_t)E_TOT * 4];           // exp(logit) per edge [E+N,4]
__device__ int g_is64;                                            // edge_index dtype flag

// ---------------- helpers --------------------------------------------------
__device__ __forceinline__ void red_add_v4(float* p, float4 v) {
    asm volatile("red.global.add.v4.f32 [%0], {%1,%2,%3,%4};"
                 :: "l"(p), "f"(v.x), "f"(v.y), "f"(v.z), "f"(v.w)
                 : "memory");
}

// Load edge i's (src, dst) regardless of whether the buffer is int32 or int64.
__device__ __forceinline__ void load_edge(const void* ei, int i, int& s, int& d) {
    if (g_is64) {
        const long long* p = (const long long*)ei;
        s = (int)p[i];
        d = (int)p[N_EDGES + i];
    } else {
        const int* p = (const int*)ei;
        s = p[i];
        d = p[N_EDGES + i];
    }
}

// ---------------- K-1: dtype detection -------------------------------------
// If data is little-endian int64 with values < 2^31, every odd int32 word is 0.
// For genuine int32 node indices, 128 consecutive odd words all zero is
// probabilistically impossible. Deterministic given fixed inputs.
__global__ void detect_dtype_kernel(const int* __restrict__ ei32) {
    if (threadIdx.x == 0 && blockIdx.x == 0) {
        int any = 0;
        for (int k = 0; k < 128; k++) any |= ei32[2 * k + 1];
        g_is64 = (any == 0) ? 1 : 0;
    }
}

// ---------------- K0: zero kernels ----------------------------------------
__global__ void zero_out_kernel(float* __restrict__ out, int n4) {
    int i = blockIdx.x * blockDim.x + threadIdx.x;
    if (i < n4) reinterpret_cast<float4*>(out)[i] = make_float4(0.f, 0.f, 0.f, 0.f);
}

__global__ void zero_denom_kernel() {
    int i = blockIdx.x * blockDim.x + threadIdx.x;
    if (i < N_NODES) reinterpret_cast<float4*>(g_denom)[i] = make_float4(0.f, 0.f, 0.f, 0.f);
}

// ---------------- K1: GEMM xp = x @ W  (fp32, smem-tiled) ------------------
#define BM 128
#define BN 64
#define BK 16

__global__ __launch_bounds__(256) void gemm_xp_kernel(
    const float* __restrict__ X, const float* __restrict__ Wm)
{
    __shared__ float As[BK][BM];
    __shared__ float Bs[BK][BN];

    const int m0 = blockIdx.x * BM;
    const int n0 = blockIdx.y * BN;
    const int tid = threadIdx.x;
    const int tx = tid & 15;   // 0..15 -> 4 output cols each
    const int ty = tid >> 4;   // 0..15 -> 8 output rows each

    float acc[8][4];
#pragma unroll
    for (int i = 0; i < 8; i++)
#pragma unroll
        for (int j = 0; j < 4; j++) acc[i][j] = 0.f;

    for (int k0 = 0; k0 < IN_DIM; k0 += BK) {
        // load A tile (BM x BK) as 512 float4, 2 per thread, store transposed
#pragma unroll
        for (int l = 0; l < 2; l++) {
            int idx = tid + l * 256;
            int r  = idx >> 2;   // 0..127 (row in tile)
            int c4 = idx & 3;    // 0..3   (float4 within row)
            int gm = m0 + r;
            float4 v = make_float4(0.f, 0.f, 0.f, 0.f);
            if (gm < N_NODES)
                v = *reinterpret_cast<const float4*>(X + (size_t)gm * IN_DIM + k0 + c4 * 4);
            As[c4 * 4 + 0][r] = v.x;
            As[c4 * 4 + 1][r] = v.y;
            As[c4 * 4 + 2][r] = v.z;
            As[c4 * 4 + 3][r] = v.w;
        }
        // load B tile (BK x BN) as 256 float4, 1 per thread
        {
            int r  = tid >> 4;   // 0..15
            int c4 = tid & 15;   // 0..15
            float4 v = *reinterpret_cast<const float4*>(
                Wm + (size_t)(k0 + r) * OUT_DIM + n0 + c4 * 4);
            *reinterpret_cast<float4*>(&Bs[r][c4 * 4]) = v;
        }
        __syncthreads();

#pragma unroll
        for (int kk = 0; kk < BK; kk++) {
            float a[8], b[4];
#pragma unroll
            for (int i = 0; i < 8; i++) a[i] = As[kk][ty * 8 + i];
#pragma unroll
            for (int j = 0; j < 4; j++) b[j] = Bs[kk][tx * 4 + j];
#pragma unroll
            for (int i = 0; i < 8; i++)
#pragma unroll
                for (int j = 0; j < 4; j++) acc[i][j] += a[i] * b[j];
        }
        __syncthreads();
    }

#pragma unroll
    for (int i = 0; i < 8; i++) {
        int gm = m0 + ty * 8 + i;
        if (gm < N_NODES) {
            float4 v = make_float4(acc[i][0], acc[i][1], acc[i][2], acc[i][3]);
            *reinterpret_cast<float4*>(g_xp + (size_t)gm * OUT_DIM + n0 + tx * 4) = v;
        }
    }
}

// ---------------- K2: per-node attention scores ----------------------------
// warp per node: a_src[n,h] = dot(xp[n,h,:], att_src[h,:]), same for dst
__global__ __launch_bounds__(256) void attn_scores_kernel(
    const float* __restrict__ att_src, const float* __restrict__ att_dst)
{
    int warp = (blockIdx.x * blockDim.x + threadIdx.x) >> 5;
    if (warp >= N_NODES) return;
    int lane = threadIdx.x & 31;
    const float* row = g_xp + (size_t)warp * OUT_DIM;

    float ps[4], pd[4];
#pragma unroll
    for (int h = 0; h < 4; h++) {
        int p0 = h * 64 + lane;
        int p1 = p0 + 32;
        float x0 = row[p0], x1 = row[p1];
        ps[h] = x0 * att_src[p0] + x1 * att_src[p1];
        pd[h] = x0 * att_dst[p0] + x1 * att_dst[p1];
    }
#pragma unroll
    for (int off = 16; off > 0; off >>= 1) {
#pragma unroll
        for (int h = 0; h < 4; h++) {
            ps[h] += __shfl_down_sync(0xffffffffu, ps[h], off);
            pd[h] += __shfl_down_sync(0xffffffffu, pd[h], off);
        }
    }
    if (lane == 0) {
#pragma unroll
        for (int h = 0; h < 4; h++) {
            g_asrc[warp * 4 + h] = ps[h];
            g_adst[warp * 4 + h] = pd[h];
        }
    }
}

// ---------------- K3: edge logits -> exp, accumulate denominators ----------
// Softmax shift-invariance: skip the segment-max (logits are O(10), exp safe).
__global__ __launch_bounds__(256) void edge_logits_kernel(const void* __restrict__ ei)
{
    int i = blockIdx.x * blockDim.x + threadIdx.x;
    if (i >= E_TOT) return;
    int s, d;
    if (i < N_EDGES) {
        load_edge(ei, i, s, d);
    } else {
        s = d = i - N_EDGES;   // self-loop
    }
    float4 as = *reinterpret_cast<const float4*>(g_asrc + s * 4);
    float4 ad = *reinterpret_cast<const float4*>(g_adst + d * 4);
    float e0 = as.x + ad.x, e1 = as.y + ad.y, e2 = as.z + ad.z, e3 = as.w + ad.w;
    e0 = (e0 > 0.f) ? e0 : NEG_SLOPE * e0;
    e1 = (e1 > 0.f) ? e1 : NEG_SLOPE * e1;
    e2 = (e2 > 0.f) ? e2 : NEG_SLOPE * e2;
    e3 = (e3 > 0.f) ? e3 : NEG_SLOPE * e3;
    float4 ee = make_float4(expf(e0), expf(e1), expf(e2), expf(e3));
    *reinterpret_cast<float4*>(g_ee + (size_t)i * 4) = ee;
    red_add_v4(g_denom + d * 4, ee);
}

// ---------------- K4: weighted scatter-aggregate ---------------------------
// warp per edge; lane handles 8 contiguous floats (one head per 8-lane group)
__global__ __launch_bounds__(256) void aggregate_kernel(
    const void* __restrict__ ei, float* __restrict__ out)
{
    int e = (blockIdx.x * blockDim.x + threadIdx.x) >> 5;
    if (e >= E_TOT) return;
    int lane = threadIdx.x & 31;
    int s, d;
    if (e < N_EDGES) {
        load_edge(ei, e, s, d);
    } else {
        s = d = e - N_EDGES;
    }
    int h = lane >> 3;  // 64 floats per head / 8 floats per lane
    float alpha = g_ee[(size_t)e * 4 + h] / g_denom[d * 4 + h];

    const float4* xs = reinterpret_cast<const float4*>(g_xp + (size_t)s * OUT_DIM + lane * 8);
    float4 v0 = xs[0], v1 = xs[1];
    v0.x *= alpha; v0.y *= alpha; v0.z *= alpha; v0.w *= alpha;
    v1.x *= alpha; v1.y *= alpha; v1.z *= alpha; v1.w *= alpha;

    float* op = out + (size_t)d * OUT_DIM + lane * 8;
    red_add_v4(op, v0);
    red_add_v4(op + 4, v1);
}

// ---------------- K5: final ReLU -------------------------------------------
__global__ void relu_kernel(float* __restrict__ out, int n4) {
    int i = blockIdx.x * blockDim.x + threadIdx.x;
    if (i < n4) {
        float4 v = reinterpret_cast<float4*>(out)[i];
        v.x = fmaxf(v.x, 0.f);
        v.y = fmaxf(v.y, 0.f);
        v.z = fmaxf(v.z, 0.f);
        v.w = fmaxf(v.w, 0.f);
        reinterpret_cast<float4*>(out)[i] = v;
    }
}

// ---------------- launch ----------------------------------------------------
extern "C" void kernel_launch(void* const* d_in, const int* in_sizes, int n_in,
                              void* d_out, int out_size)
{
    const float* x       = (const float*)d_in[0];
    const void*  ei      = d_in[1];
    const float* Wm      = (const float*)d_in[2];
    const float* att_src = (const float*)d_in[3];
    const float* att_dst = (const float*)d_in[4];
    float*       out     = (float*)d_out;

    const int out_n4 = (N_NODES * OUT_DIM) / 4;  // 3,200,000

    detect_dtype_kernel<<<1, 32>>>((const int*)ei);

    zero_out_kernel<<<(out_n4 + 255) / 256, 256>>>(out, out_n4);
    zero_denom_kernel<<<(N_NODES + 255) / 256, 256>>>();

    dim3 ggrid((N_NODES + BM - 1) / BM, OUT_DIM / BN);
    gemm_xp_kernel<<<ggrid, 256>>>(x, Wm);

    attn_scores_kernel<<<(N_NODES * 32 + 255) / 256, 256>>>(att_src, att_dst);

    edge_logits_kernel<<<(E_TOT + 255) / 256, 256>>>(ei);

    aggregate_kernel<<<((size_t)E_TOT * 32 + 255) / 256, 256>>>(ei, out);

    relu_kernel<<<(out_n4 + 255) / 256, 256>>>(out, out_n4);
}

// round 3
// speedup vs baseline: 1.2767x; 1.2767x over previous
#include <cuda_runtime.h>
#include <cstdint>

#define N_NODES 50000
#define N_EDGES 800000
#define E_TOT   (N_EDGES + N_NODES)
#define IN_DIM  256
#define OUT_DIM 256   // N_HEADS * HEAD_DIM
#define NEG_SLOPE 0.2f

// ---------------- scratch (static device globals; no runtime allocation) ---
__device__ __align__(16) float g_xp[(size_t)N_NODES * OUT_DIM];   // projected features [N,256]
__device__ __align__(16) float g_asrc[N_NODES * 4];               // per-node src logits [N,4]
__device__ __align__(16) float g_adst[N_NODES * 4];               // per-node dst logits [N,4]
__device__ __align__(16) float g_denom[N_NODES * 4];              // softmax denominators [N,4]
__device__ __align__(16) float g_ee[(size_t)E_TOT * 4];           // exp(logit) per edge [E+N,4]
__device__ int g_is64;                                            // edge_index dtype flag

// ---------------- helpers --------------------------------------------------
__device__ __forceinline__ void red_add_v4(float* p, float4 v) {
    asm volatile("red.global.add.v4.f32 [%0], {%1,%2,%3,%4};"
                 :: "l"(p), "f"(v.x), "f"(v.y), "f"(v.z), "f"(v.w)
                 : "memory");
}

__device__ __forceinline__ uint32_t f2tf32(float f) {
    uint32_t r;
    asm("cvt.rna.tf32.f32 %0, %1;" : "=r"(r) : "f"(f));
    return r;
}

// Load edge i's (src, dst) regardless of whether the buffer is int32 or int64.
__device__ __forceinline__ void load_edge(const void* ei, int i, int& s, int& d) {
    if (g_is64) {
        const long long* p = (const long long*)ei;
        s = (int)p[i];
        d = (int)p[N_EDGES + i];
    } else {
        const int* p = (const int*)ei;
        s = p[i];
        d = p[N_EDGES + i];
    }
}

// ---------------- K-1: dtype detection -------------------------------------
__global__ void detect_dtype_kernel(const int* __restrict__ ei32) {
    if (threadIdx.x == 0 && blockIdx.x == 0) {
        int any = 0;
        for (int k = 0; k < 128; k++) any |= ei32[2 * k + 1];
        g_is64 = (any == 0) ? 1 : 0;
    }
}

// ---------------- K0: zero kernels ----------------------------------------
__global__ void zero_out_kernel(float* __restrict__ out, int n4) {
    int i = blockIdx.x * blockDim.x + threadIdx.x;
    if (i < n4) reinterpret_cast<float4*>(out)[i] = make_float4(0.f, 0.f, 0.f, 0.f);
}

__global__ void zero_denom_kernel() {
    int i = blockIdx.x * blockDim.x + threadIdx.x;
    if (i < N_NODES) reinterpret_cast<float4*>(g_denom)[i] = make_float4(0.f, 0.f, 0.f, 0.f);
}

// ---------------- K1: GEMM xp = x @ W  (tf32 mma.sync) ---------------------
// Block tile 128x128, 8 warps (2x4), warp tile 64x32, BK=32, k-step 8.
#define GBM 128
#define GBN 128
#define GBK 32
#define A_LD (GBK + 4)    // 36: conflict-free A frag loads
#define B_LD (GBN + 4)    // 132: 2-way max on B frag loads

__global__ __launch_bounds__(256) void gemm_tf32_kernel(
    const float* __restrict__ X, const float* __restrict__ Wm)
{
    __shared__ uint32_t As[GBM][A_LD];   // tf32 bits
    __shared__ uint32_t Bs[GBK][B_LD];   // tf32 bits

    const int tid  = threadIdx.x;
    const int wid  = tid >> 5;
    const int lane = tid & 31;
    const int m0 = blockIdx.x * GBM;
    const int n0 = blockIdx.y * GBN;
    const int wm = (wid & 1) * 64;       // warp row offset in block tile
    const int wn = (wid >> 1) * 32;      // warp col offset in block tile
    const int gID = lane >> 2;           // 0..7
    const int tig = lane & 3;            // 0..3

    float c[4][4][4];                    // [mtile][ntile][frag reg]
#pragma unroll
    for (int i = 0; i < 4; i++)
#pragma unroll
        for (int j = 0; j < 4; j++)
#pragma unroll
            for (int r = 0; r < 4; r++) c[i][j][r] = 0.f;

    for (int k0 = 0; k0 < IN_DIM; k0 += GBK) {
        // Load A tile: 128 rows x 32 k = 1024 float4, 4 per thread.
#pragma unroll
        for (int l = 0; l < 4; l++) {
            int idx = tid + l * 256;
            int row = idx >> 3;          // 0..127
            int c4  = idx & 7;           // 0..7
            int gm  = m0 + row;
            float4 v = make_float4(0.f, 0.f, 0.f, 0.f);
            if (gm < N_NODES)
                v = *reinterpret_cast<const float4*>(X + (size_t)gm * IN_DIM + k0 + c4 * 4);
            As[row][c4 * 4 + 0] = f2tf32(v.x);
            As[row][c4 * 4 + 1] = f2tf32(v.y);
            As[row][c4 * 4 + 2] = f2tf32(v.z);
            As[row][c4 * 4 + 3] = f2tf32(v.w);
        }
        // Load B tile: 32 k-rows x 128 n = 1024 float4, 4 per thread.
#pragma unroll
        for (int l = 0; l < 4; l++) {
            int idx = tid + l * 256;
            int kr = idx >> 5;           // 0..31
            int c4 = idx & 31;           // 0..31
            float4 v = *reinterpret_cast<const float4*>(
                Wm + (size_t)(k0 + kr) * OUT_DIM + n0 + c4 * 4);
            Bs[kr][c4 * 4 + 0] = f2tf32(v.x);
            Bs[kr][c4 * 4 + 1] = f2tf32(v.y);
            Bs[kr][c4 * 4 + 2] = f2tf32(v.z);
            Bs[kr][c4 * 4 + 3] = f2tf32(v.w);
        }
        __syncthreads();

#pragma unroll
        for (int ks = 0; ks < 4; ks++) {
            const int kb = ks * 8;
            uint32_t a[4][4], b[4][2];
#pragma unroll
            for (int mt = 0; mt < 4; mt++) {
                int rb = wm + mt * 16;
                a[mt][0] = As[rb + gID    ][kb + tig    ];
                a[mt][1] = As[rb + gID + 8][kb + tig    ];
                a[mt][2] = As[rb + gID    ][kb + tig + 4];
                a[mt][3] = As[rb + gID + 8][kb + tig + 4];
            }
#pragma unroll
            for (int nt = 0; nt < 4; nt++) {
                int col = wn + nt * 8 + gID;
                b[nt][0] = Bs[kb + tig    ][col];
                b[nt][1] = Bs[kb + tig + 4][col];
            }
#pragma unroll
            for (int mt = 0; mt < 4; mt++)
#pragma unroll
                for (int nt = 0; nt < 4; nt++) {
                    asm volatile(
                        "mma.sync.aligned.m16n8k8.row.col.f32.tf32.tf32.f32 "
                        "{%0,%1,%2,%3}, {%4,%5,%6,%7}, {%8,%9}, {%0,%1,%2,%3};"
                        : "+f"(c[mt][nt][0]), "+f"(c[mt][nt][1]),
                          "+f"(c[mt][nt][2]), "+f"(c[mt][nt][3])
                        : "r"(a[mt][0]), "r"(a[mt][1]), "r"(a[mt][2]), "r"(a[mt][3]),
                          "r"(b[nt][0]), "r"(b[nt][1]));
                }
        }
        __syncthreads();
    }

    // Epilogue: c0,c1 -> (row, 2*tig..2*tig+1); c2,c3 -> (row+8, same cols)
#pragma unroll
    for (int mt = 0; mt < 4; mt++) {
        int r0 = m0 + wm + mt * 16 + gID;
#pragma unroll
        for (int nt = 0; nt < 4; nt++) {
            int col = n0 + wn + nt * 8 + 2 * tig;
            if (r0 < N_NODES) {
                float2 v01 = make_float2(c[mt][nt][0], c[mt][nt][1]);
                *reinterpret_cast<float2*>(g_xp + (size_t)r0 * OUT_DIM + col) = v01;
            }
            if (r0 + 8 < N_NODES) {
                float2 v23 = make_float2(c[mt][nt][2], c[mt][nt][3]);
                *reinterpret_cast<float2*>(g_xp + (size_t)(r0 + 8) * OUT_DIM + col) = v23;
            }
        }
    }
}

// ---------------- K2: per-node attention scores ----------------------------
__global__ __launch_bounds__(256) void attn_scores_kernel(
    const float* __restrict__ att_src, const float* __restrict__ att_dst)
{
    int warp = (blockIdx.x * blockDim.x + threadIdx.x) >> 5;
    if (warp >= N_NODES) return;
    int lane = threadIdx.x & 31;
    const float* row = g_xp + (size_t)warp * OUT_DIM;

    float ps[4], pd[4];
#pragma unroll
    for (int h = 0; h < 4; h++) {
        int p0 = h * 64 + lane;
        int p1 = p0 + 32;
        float x0 = row[p0], x1 = row[p1];
        ps[h] = x0 * att_src[p0] + x1 * att_src[p1];
        pd[h] = x0 * att_dst[p0] + x1 * att_dst[p1];
    }
#pragma unroll
    for (int off = 16; off > 0; off >>= 1) {
#pragma unroll
        for (int h = 0; h < 4; h++) {
            ps[h] += __shfl_down_sync(0xffffffffu, ps[h], off);
            pd[h] += __shfl_down_sync(0xffffffffu, pd[h], off);
        }
    }
    if (lane == 0) {
#pragma unroll
        for (int h = 0; h < 4; h++) {
            g_asrc[warp * 4 + h] = ps[h];
            g_adst[warp * 4 + h] = pd[h];
        }
    }
}

// ---------------- K3: edge logits -> exp, accumulate denominators ----------
__global__ __launch_bounds__(256) void edge_logits_kernel(const void* __restrict__ ei)
{
    int i = blockIdx.x * blockDim.x + threadIdx.x;
    if (i >= E_TOT) return;
    int s, d;
    if (i < N_EDGES) {
        load_edge(ei, i, s, d);
    } else {
        s = d = i - N_EDGES;   // self-loop
    }
    float4 as = *reinterpret_cast<const float4*>(g_asrc + s * 4);
    float4 ad = *reinterpret_cast<const float4*>(g_adst + d * 4);
    float e0 = as.x + ad.x, e1 = as.y + ad.y, e2 = as.z + ad.z, e3 = as.w + ad.w;
    e0 = (e0 > 0.f) ? e0 : NEG_SLOPE * e0;
    e1 = (e1 > 0.f) ? e1 : NEG_SLOPE * e1;
    e2 = (e2 > 0.f) ? e2 : NEG_SLOPE * e2;
    e3 = (e3 > 0.f) ? e3 : NEG_SLOPE * e3;
    float4 ee = make_float4(expf(e0), expf(e1), expf(e2), expf(e3));
    *reinterpret_cast<float4*>(g_ee + (size_t)i * 4) = ee;
    red_add_v4(g_denom + d * 4, ee);
}

// ---------------- K4: weighted scatter-aggregate ---------------------------
__global__ __launch_bounds__(256) void aggregate_kernel(
    const void* __restrict__ ei, float* __restrict__ out)
{
    int e = (blockIdx.x * blockDim.x + threadIdx.x) >> 5;
    if (e >= E_TOT) return;
    int lane = threadIdx.x & 31;
    int s, d;
    if (e < N_EDGES) {
        load_edge(ei, e, s, d);
    } else {
        s = d = e - N_EDGES;
    }
    int h = lane >> 3;
    float alpha = g_ee[(size_t)e * 4 + h] / g_denom[d * 4 + h];

    const float4* xs = reinterpret_cast<const float4*>(g_xp + (size_t)s * OUT_DIM + lane * 8);
    float4 v0 = xs[0], v1 = xs[1];
    v0.x *= alpha; v0.y *= alpha; v0.z *= alpha; v0.w *= alpha;
    v1.x *= alpha; v1.y *= alpha; v1.z *= alpha; v1.w *= alpha;

    float* op = out + (size_t)d * OUT_DIM + lane * 8;
    red_add_v4(op, v0);
    red_add_v4(op + 4, v1);
}

// ---------------- K5: final ReLU -------------------------------------------
__global__ void relu_kernel(float* __restrict__ out, int n4) {
    int i = blockIdx.x * blockDim.x + threadIdx.x;
    if (i < n4) {
        float4 v = reinterpret_cast<float4*>(out)[i];
        v.x = fmaxf(v.x, 0.f);
        v.y = fmaxf(v.y, 0.f);
        v.z = fmaxf(v.z, 0.f);
        v.w = fmaxf(v.w, 0.f);
        reinterpret_cast<float4*>(out)[i] = v;
    }
}

// ---------------- launch ----------------------------------------------------
extern "C" void kernel_launch(void* const* d_in, const int* in_sizes, int n_in,
                              void* d_out, int out_size)
{
    const float* x       = (const float*)d_in[0];
    const void*  ei      = d_in[1];
    const float* Wm      = (const float*)d_in[2];
    const float* att_src = (const float*)d_in[3];
    const float* att_dst = (const float*)d_in[4];
    float*       out     = (float*)d_out;

    const int out_n4 = (N_NODES * OUT_DIM) / 4;

    detect_dtype_kernel<<<1, 32>>>((const int*)ei);

    zero_out_kernel<<<(out_n4 + 255) / 256, 256>>>(out, out_n4);
    zero_denom_kernel<<<(N_NODES + 255) / 256, 256>>>();

    dim3 ggrid((N_NODES + GBM - 1) / GBM, OUT_DIM / GBN);
    gemm_tf32_kernel<<<ggrid, 256>>>(x, Wm);

    attn_scores_kernel<<<(N_NODES * 32 + 255) / 256, 256>>>(att_src, att_dst);

    edge_logits_kernel<<<(E_TOT + 255) / 256, 256>>>(ei);

    aggregate_kernel<<<((size_t)E_TOT * 32 + 255) / 256, 256>>>(ei, out);

    relu_kernel<<<(out_n4 + 255) / 256, 256>>>(out, out_n4);
}

// round 4
// speedup vs baseline: 1.8124x; 1.4196x over previous
#include <cuda_runtime.h>
#include <cstdint>

#define N_NODES 50000
#define N_EDGES 800000
#define E_TOT   (N_EDGES + N_NODES)
#define IN_DIM  256
#define OUT_DIM 256   // N_HEADS * HEAD_DIM
#define NEG_SLOPE 0.2f

// ---------------- scratch (static device globals; no runtime allocation) ---
__device__ __align__(16) float g_xp[(size_t)N_NODES * OUT_DIM];   // projected features [N,256]
__device__ __align__(16) float g_asrc[N_NODES * 4];               // per-node src logits [N,4]
__device__ __align__(16) float g_adst[N_NODES * 4];               // per-node dst logits [N,4]
__device__ __align__(16) float g_csr_ee[(size_t)E_TOT * 4];       // exp(logit), CSR order [E+N,4]
__device__ int g_csr_src[E_TOT];                                  // src node id, CSR order
__device__ int g_deg[N_NODES];                                    // in-degree histogram
__device__ int g_off[N_NODES];                                    // CSR row start
__device__ int g_cur[N_NODES];                                    // scatter cursor -> row end
__device__ int g_is64;                                            // edge_index dtype flag

// ---------------- helpers --------------------------------------------------
__device__ __forceinline__ uint32_t f2tf32(float f) {
    uint32_t r;
    asm("cvt.rna.tf32.f32 %0, %1;" : "=r"(r) : "f"(f));
    return r;
}

// Load edge i's (src, dst) regardless of whether the buffer is int32 or int64.
__device__ __forceinline__ void load_edge(const void* ei, int i, int& s, int& d) {
    if (g_is64) {
        const long long* p = (const long long*)ei;
        s = (int)p[i];
        d = (int)p[N_EDGES + i];
    } else {
        const int* p = (const int*)ei;
        s = p[i];
        d = p[N_EDGES + i];
    }
}

// ---------------- K-1: dtype detection -------------------------------------
__global__ void detect_dtype_kernel(const int* __restrict__ ei32) {
    if (threadIdx.x == 0 && blockIdx.x == 0) {
        int any = 0;
        for (int k = 0; k < 128; k++) any |= ei32[2 * k + 1];
        g_is64 = (any == 0) ? 1 : 0;
    }
}

// ---------------- K0: zero degree histogram --------------------------------
__global__ void zero_deg_kernel() {
    int i = blockIdx.x * blockDim.x + threadIdx.x;
    if (i < N_NODES) g_deg[i] = 0;
}

// ---------------- K1: GEMM xp = x @ W  (tf32 mma.sync) ---------------------
#define GBM 128
#define GBN 128
#define GBK 32
#define A_LD (GBK + 4)
#define B_LD (GBN + 4)

__global__ __launch_bounds__(256) void gemm_tf32_kernel(
    const float* __restrict__ X, const float* __restrict__ Wm)
{
    __shared__ uint32_t As[GBM][A_LD];
    __shared__ uint32_t Bs[GBK][B_LD];

    const int tid  = threadIdx.x;
    const int wid  = tid >> 5;
    const int lane = tid & 31;
    const int m0 = blockIdx.x * GBM;
    const int n0 = blockIdx.y * GBN;
    const int wm = (wid & 1) * 64;
    const int wn = (wid >> 1) * 32;
    const int gID = lane >> 2;
    const int tig = lane & 3;

    float c[4][4][4];
#pragma unroll
    for (int i = 0; i < 4; i++)
#pragma unroll
        for (int j = 0; j < 4; j++)
#pragma unroll
            for (int r = 0; r < 4; r++) c[i][j][r] = 0.f;

    for (int k0 = 0; k0 < IN_DIM; k0 += GBK) {
#pragma unroll
        for (int l = 0; l < 4; l++) {
            int idx = tid + l * 256;
            int row = idx >> 3;
            int c4  = idx & 7;
            int gm  = m0 + row;
            float4 v = make_float4(0.f, 0.f, 0.f, 0.f);
            if (gm < N_NODES)
                v = *reinterpret_cast<const float4*>(X + (size_t)gm * IN_DIM + k0 + c4 * 4);
            As[row][c4 * 4 + 0] = f2tf32(v.x);
            As[row][c4 * 4 + 1] = f2tf32(v.y);
            As[row][c4 * 4 + 2] = f2tf32(v.z);
            As[row][c4 * 4 + 3] = f2tf32(v.w);
        }
#pragma unroll
        for (int l = 0; l < 4; l++) {
            int idx = tid + l * 256;
            int kr = idx >> 5;
            int c4 = idx & 31;
            float4 v = *reinterpret_cast<const float4*>(
                Wm + (size_t)(k0 + kr) * OUT_DIM + n0 + c4 * 4);
            Bs[kr][c4 * 4 + 0] = f2tf32(v.x);
            Bs[kr][c4 * 4 + 1] = f2tf32(v.y);
            Bs[kr][c4 * 4 + 2] = f2tf32(v.z);
            Bs[kr][c4 * 4 + 3] = f2tf32(v.w);
        }
        __syncthreads();

#pragma unroll
        for (int ks = 0; ks < 4; ks++) {
            const int kb = ks * 8;
            uint32_t a[4][4], b[4][2];
#pragma unroll
            for (int mt = 0; mt < 4; mt++) {
                int rb = wm + mt * 16;
                a[mt][0] = As[rb + gID    ][kb + tig    ];
                a[mt][1] = As[rb + gID + 8][kb + tig    ];
                a[mt][2] = As[rb + gID    ][kb + tig + 4];
                a[mt][3] = As[rb + gID + 8][kb + tig + 4];
            }
#pragma unroll
            for (int nt = 0; nt < 4; nt++) {
                int col = wn + nt * 8 + gID;
                b[nt][0] = Bs[kb + tig    ][col];
                b[nt][1] = Bs[kb + tig + 4][col];
            }
#pragma unroll
            for (int mt = 0; mt < 4; mt++)
#pragma unroll
                for (int nt = 0; nt < 4; nt++) {
                    asm volatile(
                        "mma.sync.aligned.m16n8k8.row.col.f32.tf32.tf32.f32 "
                        "{%0,%1,%2,%3}, {%4,%5,%6,%7}, {%8,%9}, {%0,%1,%2,%3};"
                        : "+f"(c[mt][nt][0]), "+f"(c[mt][nt][1]),
                          "+f"(c[mt][nt][2]), "+f"(c[mt][nt][3])
                        : "r"(a[mt][0]), "r"(a[mt][1]), "r"(a[mt][2]), "r"(a[mt][3]),
                          "r"(b[nt][0]), "r"(b[nt][1]));
                }
        }
        __syncthreads();
    }

#pragma unroll
    for (int mt = 0; mt < 4; mt++) {
        int r0 = m0 + wm + mt * 16 + gID;
#pragma unroll
        for (int nt = 0; nt < 4; nt++) {
            int col = n0 + wn + nt * 8 + 2 * tig;
            if (r0 < N_NODES) {
                float2 v01 = make_float2(c[mt][nt][0], c[mt][nt][1]);
                *reinterpret_cast<float2*>(g_xp + (size_t)r0 * OUT_DIM + col) = v01;
            }
            if (r0 + 8 < N_NODES) {
                float2 v23 = make_float2(c[mt][nt][2], c[mt][nt][3]);
                *reinterpret_cast<float2*>(g_xp + (size_t)(r0 + 8) * OUT_DIM + col) = v23;
            }
        }
    }
}

// ---------------- K2: per-node attention scores ----------------------------
__global__ __launch_bounds__(256) void attn_scores_kernel(
    const float* __restrict__ att_src, const float* __restrict__ att_dst)
{
    int warp = (blockIdx.x * blockDim.x + threadIdx.x) >> 5;
    if (warp >= N_NODES) return;
    int lane = threadIdx.x & 31;
    const float* row = g_xp + (size_t)warp * OUT_DIM;

    float ps[4], pd[4];
#pragma unroll
    for (int h = 0; h < 4; h++) {
        int p0 = h * 64 + lane;
        int p1 = p0 + 32;
        float x0 = row[p0], x1 = row[p1];
        ps[h] = x0 * att_src[p0] + x1 * att_src[p1];
        pd[h] = x0 * att_dst[p0] + x1 * att_dst[p1];
    }
#pragma unroll
    for (int off = 16; off > 0; off >>= 1) {
#pragma unroll
        for (int h = 0; h < 4; h++) {
            ps[h] += __shfl_down_sync(0xffffffffu, ps[h], off);
            pd[h] += __shfl_down_sync(0xffffffffu, pd[h], off);
        }
    }
    if (lane == 0) {
#pragma unroll
        for (int h = 0; h < 4; h++) {
            g_asrc[warp * 4 + h] = ps[h];
            g_adst[warp * 4 + h] = pd[h];
        }
    }
}

// ---------------- K3a: in-degree histogram ---------------------------------
__global__ __launch_bounds__(256) void hist_kernel(const void* __restrict__ ei)
{
    int i = blockIdx.x * blockDim.x + threadIdx.x;
    if (i >= E_TOT) return;
    int s, d;
    if (i < N_EDGES) load_edge(ei, i, s, d);
    else             d = i - N_EDGES;
    atomicAdd(&g_deg[d], 1);
}

// ---------------- K3b: single-block exclusive scan -> offsets + cursors ----
#define SCAN_T 1024
__global__ __launch_bounds__(SCAN_T) void scan_kernel()
{
    __shared__ int sums[SCAN_T];
    const int t = threadIdx.x;
    const int CH = (N_NODES + SCAN_T - 1) / SCAN_T;   // 49
    const int lo = t * CH;
    const int hi = (lo + CH < N_NODES) ? lo + CH : N_NODES;

    int s = 0;
    for (int i = lo; i < hi; i++) s += g_deg[i];
    sums[t] = s;
    __syncthreads();

    // inclusive Hillis-Steele scan over block sums
    for (int off = 1; off < SCAN_T; off <<= 1) {
        int v = (t >= off) ? sums[t - off] : 0;
        __syncthreads();
        sums[t] += v;
        __syncthreads();
    }

    int run = (t == 0) ? 0 : sums[t - 1];
    for (int i = lo; i < hi; i++) {
        int dg = g_deg[i];
        g_off[i] = run;
        g_cur[i] = run;
        run += dg;
    }
}

// ---------------- K3c: scatter edges into CSR order + compute exp(logit) ---
__global__ __launch_bounds__(256) void scatter_kernel(const void* __restrict__ ei)
{
    int i = blockIdx.x * blockDim.x + threadIdx.x;
    if (i >= E_TOT) return;
    int s, d;
    if (i < N_EDGES) load_edge(ei, i, s, d);
    else             s = d = i - N_EDGES;   // self-loop

    float4 as = *reinterpret_cast<const float4*>(g_asrc + s * 4);
    float4 ad = *reinterpret_cast<const float4*>(g_adst + d * 4);
    float e0 = as.x + ad.x, e1 = as.y + ad.y, e2 = as.z + ad.z, e3 = as.w + ad.w;
    e0 = (e0 > 0.f) ? e0 : NEG_SLOPE * e0;
    e1 = (e1 > 0.f) ? e1 : NEG_SLOPE * e1;
    e2 = (e2 > 0.f) ? e2 : NEG_SLOPE * e2;
    e3 = (e3 > 0.f) ? e3 : NEG_SLOPE * e3;
    float4 ee = make_float4(__expf(e0), __expf(e1), __expf(e2), __expf(e3));

    int pos = atomicAdd(&g_cur[d], 1);
    g_csr_src[pos] = s;
    *reinterpret_cast<float4*>(g_csr_ee + (size_t)pos * 4) = ee;
}

// ---------------- K4: CSR aggregate, atomic-free, fused softmax + ReLU -----
// One warp per dst node. out[d] = relu( (sum_e ee_e * xp[src_e]) / (sum_e ee_e) )
__global__ __launch_bounds__(256) void aggregate_csr_kernel(float* __restrict__ out)
{
    int d = (blockIdx.x * blockDim.x + threadIdx.x) >> 5;
    if (d >= N_NODES) return;
    int lane = threadIdx.x & 31;
    int h = lane >> 3;                    // head for this lane's 8 floats
    int beg = g_off[d];
    int end = g_cur[d];                   // after scatter, cursor == row end

    float acc0x = 0.f, acc0y = 0.f, acc0z = 0.f, acc0w = 0.f;
    float acc1x = 0.f, acc1y = 0.f, acc1z = 0.f, acc1w = 0.f;
    float denom = 0.f;

    for (int j = beg; j < end; j++) {
        int   s  = g_csr_src[j];
        float ee = g_csr_ee[(size_t)j * 4 + h];
        denom += ee;
        const float4* xs = reinterpret_cast<const float4*>(
            g_xp + (size_t)s * OUT_DIM + lane * 8);
        float4 v0 = xs[0], v1 = xs[1];
        acc0x += ee * v0.x; acc0y += ee * v0.y; acc0z += ee * v0.z; acc0w += ee * v0.w;
        acc1x += ee * v1.x; acc1y += ee * v1.y; acc1z += ee * v1.z; acc1w += ee * v1.w;
    }

    float inv = 1.f / denom;
    float4 o0 = make_float4(fmaxf(acc0x * inv, 0.f), fmaxf(acc0y * inv, 0.f),
                            fmaxf(acc0z * inv, 0.f), fmaxf(acc0w * inv, 0.f));
    float4 o1 = make_float4(fmaxf(acc1x * inv, 0.f), fmaxf(acc1y * inv, 0.f),
                            fmaxf(acc1z * inv, 0.f), fmaxf(acc1w * inv, 0.f));
    float4* op = reinterpret_cast<float4*>(out + (size_t)d * OUT_DIM + lane * 8);
    op[0] = o0;
    op[1] = o1;
}

// ---------------- launch ----------------------------------------------------
extern "C" void kernel_launch(void* const* d_in, const int* in_sizes, int n_in,
                              void* d_out, int out_size)
{
    const float* x       = (const float*)d_in[0];
    const void*  ei      = d_in[1];
    const float* Wm      = (const float*)d_in[2];
    const float* att_src = (const float*)d_in[3];
    const float* att_dst = (const float*)d_in[4];
    float*       out     = (float*)d_out;

    detect_dtype_kernel<<<1, 32>>>((const int*)ei);
    zero_deg_kernel<<<(N_NODES + 255) / 256, 256>>>();

    dim3 ggrid((N_NODES + GBM - 1) / GBM, OUT_DIM / GBN);
    gemm_tf32_kernel<<<ggrid, 256>>>(x, Wm);

    attn_scores_kernel<<<(N_NODES * 32 + 255) / 256, 256>>>(att_src, att_dst);

    hist_kernel<<<(E_TOT + 255) / 256, 256>>>(ei);
    scan_kernel<<<1, SCAN_T>>>();
    scatter_kernel<<<(E_TOT + 255) / 256, 256>>>(ei);

    aggregate_csr_kernel<<<((size_t)N_NODES * 32 + 255) / 256, 256>>>(out);
}

// round 5
// speedup vs baseline: 2.0146x; 1.1116x over previous
#include <cuda_runtime.h>
#include <cuda_fp16.h>
#include <cstdint>

#define N_NODES 50000
#define N_EDGES 800000
#define E_TOT   (N_EDGES + N_NODES)
#define IN_DIM  256
#define OUT_DIM 256   // N_HEADS * HEAD_DIM
#define NEG_SLOPE 0.2f

// ---------------- scratch (static device globals; no runtime allocation) ---
__device__ __align__(16) __half g_xph[(size_t)N_NODES * OUT_DIM]; // projected features, fp16 [N,256]
__device__ __align__(16) float g_asrc[N_NODES * 4];               // per-node src logits [N,4]
__device__ __align__(16) float g_adst[N_NODES * 4];               // per-node dst logits [N,4]
__device__ __align__(16) float g_csr_ee[(size_t)E_TOT * 4];       // exp(logit), CSR order [E+N,4]
__device__ int g_csr_src[E_TOT];                                  // src node id, CSR order
__device__ int g_deg[N_NODES];                                    // in-degree histogram
__device__ int g_off[N_NODES];                                    // CSR row start
__device__ int g_cur[N_NODES];                                    // scatter cursor -> row end
__device__ int g_is64;                                            // edge_index dtype flag

// ---------------- helpers --------------------------------------------------
__device__ __forceinline__ uint32_t f2tf32(float f) {
    uint32_t r;
    asm("cvt.rna.tf32.f32 %0, %1;" : "=r"(r) : "f"(f));
    return r;
}

__device__ __forceinline__ void load_edge(const void* ei, int i, int& s, int& d) {
    if (g_is64) {
        const long long* p = (const long long*)ei;
        s = (int)p[i];
        d = (int)p[N_EDGES + i];
    } else {
        const int* p = (const int*)ei;
        s = p[i];
        d = p[N_EDGES + i];
    }
}

// ---------------- K-1: dtype detection -------------------------------------
__global__ void detect_dtype_kernel(const int* __restrict__ ei32) {
    if (threadIdx.x == 0 && blockIdx.x == 0) {
        int any = 0;
        for (int k = 0; k < 128; k++) any |= ei32[2 * k + 1];
        g_is64 = (any == 0) ? 1 : 0;
    }
}

// ---------------- K0: zero degree histogram --------------------------------
__global__ void zero_deg_kernel() {
    int i = blockIdx.x * blockDim.x + threadIdx.x;
    if (i < N_NODES) g_deg[i] = 0;
}

// ---------------- K1: GEMM xp = x @ W  (tf32 mma.sync, fp16 output) --------
#define GBM 128
#define GBN 128
#define GBK 32
#define A_LD (GBK + 4)
#define B_LD (GBN + 4)

__global__ __launch_bounds__(256) void gemm_tf32_kernel(
    const float* __restrict__ X, const float* __restrict__ Wm)
{
    __shared__ uint32_t As[GBM][A_LD];
    __shared__ uint32_t Bs[GBK][B_LD];

    const int tid  = threadIdx.x;
    const int wid  = tid >> 5;
    const int lane = tid & 31;
    const int m0 = blockIdx.x * GBM;
    const int n0 = blockIdx.y * GBN;
    const int wm = (wid & 1) * 64;
    const int wn = (wid >> 1) * 32;
    const int gID = lane >> 2;
    const int tig = lane & 3;

    float c[4][4][4];
#pragma unroll
    for (int i = 0; i < 4; i++)
#pragma unroll
        for (int j = 0; j < 4; j++)
#pragma unroll
            for (int r = 0; r < 4; r++) c[i][j][r] = 0.f;

    for (int k0 = 0; k0 < IN_DIM; k0 += GBK) {
#pragma unroll
        for (int l = 0; l < 4; l++) {
            int idx = tid + l * 256;
            int row = idx >> 3;
            int c4  = idx & 7;
            int gm  = m0 + row;
            float4 v = make_float4(0.f, 0.f, 0.f, 0.f);
            if (gm < N_NODES)
                v = *reinterpret_cast<const float4*>(X + (size_t)gm * IN_DIM + k0 + c4 * 4);
            As[row][c4 * 4 + 0] = f2tf32(v.x);
            As[row][c4 * 4 + 1] = f2tf32(v.y);
            As[row][c4 * 4 + 2] = f2tf32(v.z);
            As[row][c4 * 4 + 3] = f2tf32(v.w);
        }
#pragma unroll
        for (int l = 0; l < 4; l++) {
            int idx = tid + l * 256;
            int kr = idx >> 5;
            int c4 = idx & 31;
            float4 v = *reinterpret_cast<const float4*>(
                Wm + (size_t)(k0 + kr) * OUT_DIM + n0 + c4 * 4);
            Bs[kr][c4 * 4 + 0] = f2tf32(v.x);
            Bs[kr][c4 * 4 + 1] = f2tf32(v.y);
            Bs[kr][c4 * 4 + 2] = f2tf32(v.z);
            Bs[kr][c4 * 4 + 3] = f2tf32(v.w);
        }
        __syncthreads();

#pragma unroll
        for (int ks = 0; ks < 4; ks++) {
            const int kb = ks * 8;
            uint32_t a[4][4], b[4][2];
#pragma unroll
            for (int mt = 0; mt < 4; mt++) {
                int rb = wm + mt * 16;
                a[mt][0] = As[rb + gID    ][kb + tig    ];
                a[mt][1] = As[rb + gID + 8][kb + tig    ];
                a[mt][2] = As[rb + gID    ][kb + tig + 4];
                a[mt][3] = As[rb + gID + 8][kb + tig + 4];
            }
#pragma unroll
            for (int nt = 0; nt < 4; nt++) {
                int col = wn + nt * 8 + gID;
                b[nt][0] = Bs[kb + tig    ][col];
                b[nt][1] = Bs[kb + tig + 4][col];
            }
#pragma unroll
            for (int mt = 0; mt < 4; mt++)
#pragma unroll
                for (int nt = 0; nt < 4; nt++) {
                    asm volatile(
                        "mma.sync.aligned.m16n8k8.row.col.f32.tf32.tf32.f32 "
                        "{%0,%1,%2,%3}, {%4,%5,%6,%7}, {%8,%9}, {%0,%1,%2,%3};"
                        : "+f"(c[mt][nt][0]), "+f"(c[mt][nt][1]),
                          "+f"(c[mt][nt][2]), "+f"(c[mt][nt][3])
                        : "r"(a[mt][0]), "r"(a[mt][1]), "r"(a[mt][2]), "r"(a[mt][3]),
                          "r"(b[nt][0]), "r"(b[nt][1]));
                }
        }
        __syncthreads();
    }

    // Epilogue: write fp16. c0,c1 -> (row, 2*tig..+1); c2,c3 -> (row+8, same)
#pragma unroll
    for (int mt = 0; mt < 4; mt++) {
        int r0 = m0 + wm + mt * 16 + gID;
#pragma unroll
        for (int nt = 0; nt < 4; nt++) {
            int col = n0 + wn + nt * 8 + 2 * tig;
            if (r0 < N_NODES) {
                __half2 v01 = __floats2half2_rn(c[mt][nt][0], c[mt][nt][1]);
                *reinterpret_cast<__half2*>(g_xph + (size_t)r0 * OUT_DIM + col) = v01;
            }
            if (r0 + 8 < N_NODES) {
                __half2 v23 = __floats2half2_rn(c[mt][nt][2], c[mt][nt][3]);
                *reinterpret_cast<__half2*>(g_xph + (size_t)(r0 + 8) * OUT_DIM + col) = v23;
            }
        }
    }
}

// ---------------- K2: per-node attention scores (fp16 xp) ------------------
__global__ __launch_bounds__(256) void attn_scores_kernel(
    const float* __restrict__ att_src, const float* __restrict__ att_dst)
{
    int warp = (blockIdx.x * blockDim.x + threadIdx.x) >> 5;
    if (warp >= N_NODES) return;
    int lane = threadIdx.x & 31;
    const __half2* row = reinterpret_cast<const __half2*>(g_xph + (size_t)warp * OUT_DIM);

    float ps[4], pd[4];
#pragma unroll
    for (int h = 0; h < 4; h++) {
        int c2 = h * 32 + lane;                 // half2 index; cols 2*c2, 2*c2+1
        float2 f = __half22float2(row[c2]);
        int col = 2 * c2;
        ps[h] = f.x * att_src[col] + f.y * att_src[col + 1];
        pd[h] = f.x * att_dst[col] + f.y * att_dst[col + 1];
    }
#pragma unroll
    for (int off = 16; off > 0; off >>= 1) {
#pragma unroll
        for (int h = 0; h < 4; h++) {
            ps[h] += __shfl_down_sync(0xffffffffu, ps[h], off);
            pd[h] += __shfl_down_sync(0xffffffffu, pd[h], off);
        }
    }
    if (lane == 0) {
#pragma unroll
        for (int h = 0; h < 4; h++) {
            g_asrc[warp * 4 + h] = ps[h];
            g_adst[warp * 4 + h] = pd[h];
        }
    }
}

// ---------------- K3a: in-degree histogram ---------------------------------
__global__ __launch_bounds__(256) void hist_kernel(const void* __restrict__ ei)
{
    int i = blockIdx.x * blockDim.x + threadIdx.x;
    if (i >= E_TOT) return;
    int s, d;
    if (i < N_EDGES) load_edge(ei, i, s, d);
    else             d = i - N_EDGES;
    atomicAdd(&g_deg[d], 1);
}

// ---------------- K3b: single-block exclusive scan -> offsets + cursors ----
#define SCAN_T 1024
__global__ __launch_bounds__(SCAN_T) void scan_kernel()
{
    __shared__ int sums[SCAN_T];
    const int t = threadIdx.x;
    const int CH = (N_NODES + SCAN_T - 1) / SCAN_T;   // 49
    const int lo = t * CH;
    const int hi = (lo + CH < N_NODES) ? lo + CH : N_NODES;

    int s = 0;
    for (int i = lo; i < hi; i++) s += g_deg[i];
    sums[t] = s;
    __syncthreads();

    for (int off = 1; off < SCAN_T; off <<= 1) {
        int v = (t >= off) ? sums[t - off] : 0;
        __syncthreads();
        sums[t] += v;
        __syncthreads();
    }

    int run = (t == 0) ? 0 : sums[t - 1];
    for (int i = lo; i < hi; i++) {
        int dg = g_deg[i];
        g_off[i] = run;
        g_cur[i] = run;
        run += dg;
    }
}

// ---------------- K3c: scatter edges into CSR order + compute exp(logit) ---
__global__ __launch_bounds__(256) void scatter_kernel(const void* __restrict__ ei)
{
    int i = blockIdx.x * blockDim.x + threadIdx.x;
    if (i >= E_TOT) return;
    int s, d;
    if (i < N_EDGES) load_edge(ei, i, s, d);
    else             s = d = i - N_EDGES;   // self-loop

    float4 as = *reinterpret_cast<const float4*>(g_asrc + s * 4);
    float4 ad = *reinterpret_cast<const float4*>(g_adst + d * 4);
    float e0 = as.x + ad.x, e1 = as.y + ad.y, e2 = as.z + ad.z, e3 = as.w + ad.w;
    e0 = (e0 > 0.f) ? e0 : NEG_SLOPE * e0;
    e1 = (e1 > 0.f) ? e1 : NEG_SLOPE * e1;
    e2 = (e2 > 0.f) ? e2 : NEG_SLOPE * e2;
    e3 = (e3 > 0.f) ? e3 : NEG_SLOPE * e3;
    float4 ee = make_float4(__expf(e0), __expf(e1), __expf(e2), __expf(e3));

    int pos = atomicAdd(&g_cur[d], 1);
    g_csr_src[pos] = s;
    *reinterpret_cast<float4*>(g_csr_ee + (size_t)pos * 4) = ee;
}

// ---------------- K4: CSR aggregate (fp16 gather), fused softmax + ReLU ----
// One warp per dst node. Lane covers 8 halves (=16B, one uint4). h = lane>>3.
__global__ __launch_bounds__(256) void aggregate_csr_kernel(float* __restrict__ out)
{
    int d = (blockIdx.x * blockDim.x + threadIdx.x) >> 5;
    if (d >= N_NODES) return;
    int lane = threadIdx.x & 31;
    int h = lane >> 3;
    int beg = g_off[d];
    int end = g_cur[d];

    float a0 = 0.f, a1 = 0.f, a2 = 0.f, a3 = 0.f;
    float a4 = 0.f, a5 = 0.f, a6 = 0.f, a7 = 0.f;
    float denom = 0.f;

    for (int j = beg; j < end; j++) {
        int   s  = g_csr_src[j];
        float ee = g_csr_ee[(size_t)j * 4 + h];
        denom += ee;
        uint4 u = *reinterpret_cast<const uint4*>(
            g_xph + (size_t)s * OUT_DIM + lane * 8);
        const __half2* hp = reinterpret_cast<const __half2*>(&u);
        float2 f0 = __half22float2(hp[0]);
        float2 f1 = __half22float2(hp[1]);
        float2 f2 = __half22float2(hp[2]);
        float2 f3 = __half22float2(hp[3]);
        a0 += ee * f0.x; a1 += ee * f0.y;
        a2 += ee * f1.x; a3 += ee * f1.y;
        a4 += ee * f2.x; a5 += ee * f2.y;
        a6 += ee * f3.x; a7 += ee * f3.y;
    }

    float inv = 1.f / denom;
    float4 o0 = make_float4(fmaxf(a0 * inv, 0.f), fmaxf(a1 * inv, 0.f),
                            fmaxf(a2 * inv, 0.f), fmaxf(a3 * inv, 0.f));
    float4 o1 = make_float4(fmaxf(a4 * inv, 0.f), fmaxf(a5 * inv, 0.f),
                            fmaxf(a6 * inv, 0.f), fmaxf(a7 * inv, 0.f));
    float4* op = reinterpret_cast<float4*>(out + (size_t)d * OUT_DIM + lane * 8);
    op[0] = o0;
    op[1] = o1;
}

// ---------------- launch ----------------------------------------------------
extern "C" void kernel_launch(void* const* d_in, const int* in_sizes, int n_in,
                              void* d_out, int out_size)
{
    const float* x       = (const float*)d_in[0];
    const void*  ei      = d_in[1];
    const float* Wm      = (const float*)d_in[2];
    const float* att_src = (const float*)d_in[3];
    const float* att_dst = (const float*)d_in[4];
    float*       out     = (float*)d_out;

    detect_dtype_kernel<<<1, 32>>>((const int*)ei);
    zero_deg_kernel<<<(N_NODES + 255) / 256, 256>>>();

    dim3 ggrid((N_NODES + GBM - 1) / GBM, OUT_DIM / GBN);
    gemm_tf32_kernel<<<ggrid, 256>>>(x, Wm);

    attn_scores_kernel<<<(N_NODES * 32 + 255) / 256, 256>>>(att_src, att_dst);

    hist_kernel<<<(E_TOT + 255) / 256, 256>>>(ei);
    scan_kernel<<<1, SCAN_T>>>();
    scatter_kernel<<<(E_TOT + 255) / 256, 256>>>(ei);

    aggregate_csr_kernel<<<((size_t)N_NODES * 32 + 255) / 256, 256>>>(out);
}